// round 8
// baseline (speedup 1.0000x reference)
#include <cuda_runtime.h>

#define N_ENTITY 100000
#define DD 128
#define HIDSZ 256
#define N_REL 48
#define NB 8
#define NEDGE 1000000
#define N_POS 1024
#define CAP (1 << 17)
#define ZMAX (N_POS * N_REL)
#define TILE 4
#define NCHUNK 36
#define CROWS 32
#define WBUF_F (CROWS * DD)
#define PGRID 148
#define PTHREADS 1024

// ---- device scratch (no allocation allowed) ----
__device__ int   g_map[N_ENTITY];
__device__ int   g_deg[N_POS * N_REL];
__device__ float g_s[N_POS * N_REL * DD];
__device__ int4  g_ce[CAP];
__device__ int   g_cnt;
__device__ int   g_zlist[ZMAX];
__device__ int   g_zcnt;
__device__ int   g_bar_count;
__device__ volatile int g_bar_gen;

__device__ __forceinline__ void grid_bar() {
    __syncthreads();
    if (threadIdx.x == 0) {
        int gen = g_bar_gen;
        __threadfence();
        if (atomicAdd(&g_bar_count, 1) == (int)gridDim.x - 1) {
            g_bar_count = 0;
            __threadfence();
            g_bar_gen = gen + 1;
        } else {
            while (g_bar_gen == gen) { }
        }
        __threadfence();
    }
    __syncthreads();
}

// ==== Kernel A: persistent prep (P0..P4) ====
__global__ __launch_bounds__(PTHREADS)
void k_prep(const float* __restrict__ x,
            const int* __restrict__ ei, const int* __restrict__ et,
            const int* __restrict__ ids) {
    const int tid  = threadIdx.x;
    const int gtid = blockIdx.x * PTHREADS + tid;
    const int NT   = gridDim.x * PTHREADS;

    for (int i = gtid; i < N_ENTITY; i += NT) g_map[i] = 0x7fffffff;
    for (int i = gtid; i < N_POS * N_REL; i += NT) g_deg[i] = 0;
    if (gtid == 0) { g_cnt = 0; g_zcnt = 0; }
    grid_bar();

    if (gtid < N_POS) atomicMin(&g_map[ids[gtid]], gtid);
    grid_bar();

    for (int t = gtid; t < NEDGE / 4; t += NT) {
        int4 dst4 = reinterpret_cast<const int4*>(ei + NEDGE)[t];
        int ds[4] = {dst4.x, dst4.y, dst4.z, dst4.w};
#pragma unroll
        for (int q = 0; q < 4; ++q) {
            int e = t * 4 + q;
            int slot = g_map[ds[q]];
            if (slot < N_POS) {
                int rel = __ldg(&et[e]);
                int row = slot * N_REL + rel;
                int old = atomicAdd(&g_deg[row], 1);
                if (old == 1) {
                    int zp = atomicAdd(&g_zcnt, 1);
                    if (zp < ZMAX) g_zlist[zp] = row;
                }
                int p = atomicAdd(&g_cnt, 1);
                if (p < CAP) g_ce[p] = make_int4(__ldg(&ei[e]), slot, rel, 0);
            }
        }
    }
    grid_bar();

    {
        int warp = gtid >> 5, lane = tid & 31, nw = NT >> 5;
        int nz = *(volatile int*)&g_zcnt; if (nz > ZMAX) nz = ZMAX;
        float4 z = make_float4(0.f, 0.f, 0.f, 0.f);
        for (int i = warp; i < nz; i += nw) {
            int row = g_zlist[i];
            reinterpret_cast<float4*>(g_s + (size_t)row * DD)[lane] = z;
        }
    }
    grid_bar();

    {
        int warp = gtid >> 5, lane = tid & 31, nw = NT >> 5;
        int cnt = *(volatile int*)&g_cnt; if (cnt > CAP) cnt = CAP;
        for (int i = warp; i < cnt; i += nw) {
            int4 ce = g_ce[i];
            int row = ce.y * N_REL + ce.z;
            int dg = g_deg[row];
            float4 xv = reinterpret_cast<const float4*>(x + (long)ce.x * DD)[lane];
            float* sp = &g_s[(size_t)row * DD + lane * 4];
            if (dg == 1) {
                *reinterpret_cast<float4*>(sp) = xv;
            } else {
                atomicAdd(sp + 0, xv.x);
                atomicAdd(sp + 1, xv.y);
                atomicAdd(sp + 2, xv.z);
                atomicAdd(sp + 3, xv.w);
            }
        }
    }
}

// ==== Kernel B: fused per-position pipeline, TILE=4, grid 256 ====
__global__ __launch_bounds__(256)
void k_final(const float* __restrict__ x, const float* __restrict__ bases,
             const float* __restrict__ comp, const float* __restrict__ root,
             const float* __restrict__ bias,
             const float* __restrict__ w1, const float* __restrict__ b1,
             const float* __restrict__ w2, const float* __restrict__ b2,
             const float* __restrict__ wp, const float* __restrict__ bp,
             const int* __restrict__ ids, float* __restrict__ out) {
    extern __shared__ float sm[];
    float* wbuf  = sm;                       // 2 * 4096 floats (32 KB)
    float* xs    = wbuf + 2 * WBUF_F;        // 512
    float* vv    = xs + TILE * DD;           // 4096
    float* compS = vv + TILE * NB * DD;      // 384
    float* normS = compS + N_REL * NB;       // 192
    float* hb    = normS + TILE * N_REL;     // 512
    float* zb    = hb + TILE * DD;           // 256
    int*  canon  = (int*)(zb + TILE * 64);   // 4 ints

    const int tid = threadIdx.x;
    const int g   = tid >> 7;    // 0 or 1 (group); group handles positions {2g, 2g+1}
    const int d   = tid & 127;
    const int pbase = blockIdx.x * TILE;

    if (tid < TILE) canon[tid] = g_map[ids[pbase + tid]];
    for (int i = tid; i < TILE * DD; i += 256) {
        int p = i >> 7;
        xs[i] = x[(long)ids[pbase + p] * DD + (i & 127)];
    }
    for (int i = tid; i < N_REL * NB; i += 256) compS[i] = comp[i];
    __syncthreads();
    if (tid < TILE * N_REL) {   // 192 <= 256
        int p = tid / N_REL, r = tid % N_REL;
        int dg = g_deg[canon[p] * N_REL + r];
        normS[tid] = dg > 0 ? 1.0f / (float)dg : 0.0f;
    }

    float4 stage[4];
    {
        const float4* src = reinterpret_cast<const float4*>(root);
#pragma unroll
        for (int t = 0; t < 4; ++t) stage[t] = src[tid + t * 256];
    }
    __syncthreads();

    // phase 2: vv[p][k][d] = sum_{r: deg>0} norm*s*comp  (2 positions per group)
#pragma unroll
    for (int p = 0; p < 2; ++p) {
        int pp = g * 2 + p;
        const float* srow = &g_s[(size_t)canon[pp] * N_REL * DD + d];
        float acc[NB];
#pragma unroll
        for (int k = 0; k < NB; ++k) acc[k] = 0.0f;
        for (int r = 0; r < N_REL; ++r) {
            float nm = normS[pp * N_REL + r];
            if (nm != 0.0f) {
                float sv = srow[r * DD] * nm;
#pragma unroll
                for (int k = 0; k < NB; ++k) acc[k] += sv * compS[r * NB + k];
            }
        }
#pragma unroll
        for (int k = 0; k < NB; ++k) vv[(pp * NB + k) * DD + d] = acc[k];
    }
    {
        float4* dst = reinterpret_cast<float4*>(wbuf);
#pragma unroll
        for (int t = 0; t < 4; ++t) dst[tid + t * 256] = stage[t];
    }
    __syncthreads();

    // phase 3: hb = bias + xs@root + sum_k vv_k@B_k + xs
    {
        float acc0 = bias[d], acc1 = acc0;
        const int pp0 = g * 2;
        int buf = 0;
        for (int cc = 0; cc < NCHUNK; ++cc) {
            if (cc + 1 < NCHUNK) {
                int m = (cc + 1) >> 2;
                int j0 = ((cc + 1) & 3) * CROWS;
                const float* wsrc = (m == 0) ? (root + j0 * DD)
                                             : (bases + ((size_t)(m - 1) * DD + j0) * DD);
                const float4* src = reinterpret_cast<const float4*>(wsrc);
#pragma unroll
                for (int t = 0; t < 4; ++t) stage[t] = src[tid + t * 256];
            }
            {
                int m = cc >> 2;
                int j0 = (cc & 3) * CROWS;
                const float* a0 = (m == 0) ? (xs + pp0 * DD + j0)
                                           : (vv + (pp0 * NB + (m - 1)) * DD + j0);
                const float* a1 = (m == 0) ? (xs + (pp0 + 1) * DD + j0)
                                           : (vv + ((pp0 + 1) * NB + (m - 1)) * DD + j0);
                const float* wrow = wbuf + buf * WBUF_F + d;
#pragma unroll
                for (int jj4 = 0; jj4 < CROWS / 4; ++jj4) {
                    float w0 = wrow[(jj4 * 4 + 0) * DD];
                    float w1v = wrow[(jj4 * 4 + 1) * DD];
                    float w2v = wrow[(jj4 * 4 + 2) * DD];
                    float w3v = wrow[(jj4 * 4 + 3) * DD];
                    float4 v0 = reinterpret_cast<const float4*>(a0)[jj4];
                    float4 v1 = reinterpret_cast<const float4*>(a1)[jj4];
                    acc0 += v0.x * w0 + v0.y * w1v + v0.z * w2v + v0.w * w3v;
                    acc1 += v1.x * w0 + v1.y * w1v + v1.z * w2v + v1.w * w3v;
                }
            }
            if (cc + 1 < NCHUNK) {
                float4* dst = reinterpret_cast<float4*>(wbuf + (buf ^ 1) * WBUF_F);
#pragma unroll
                for (int t = 0; t < 4; ++t) dst[tid + t * 256] = stage[t];
                buf ^= 1;
            }
            __syncthreads();
        }
        hb[pp0 * DD + d]       = acc0 + xs[pp0 * DD + d];
        hb[(pp0 + 1) * DD + d] = acc1 + xs[(pp0 + 1) * DD + d];
    }
    __syncthreads();

    // stage w1 (8192 floats fills both wbuf halves)
    {
        const float4* src = reinterpret_cast<const float4*>(w1);
        float4* dst = reinterpret_cast<float4*>(wbuf);
#pragma unroll
        for (int t = 0; t < 8; ++t) dst[tid + t * 256] = src[tid + t * 256];
    }
    __syncthreads();

    // phase 5: zb[p][c] = relu(hb[p] @ w1 + b1)  (TILE*64 = 256 outputs, 1/thread)
    {
        int c = tid & 63, p = tid >> 6;   // p: 0..3
        float acc = b1[c];
        const float* wcol = wbuf + c;
        const float4* h4 = reinterpret_cast<const float4*>(hb + p * DD);
#pragma unroll 4
        for (int j4 = 0; j4 < DD / 4; ++j4) {
            float w0 = wcol[(j4 * 4 + 0) * 64];
            float w1v = wcol[(j4 * 4 + 1) * 64];
            float w2v = wcol[(j4 * 4 + 2) * 64];
            float w3v = wcol[(j4 * 4 + 3) * 64];
            float4 h = h4[j4];
            acc += h.x * w0 + h.y * w1v + h.z * w2v + h.w * w3v;
        }
        zb[p * 64 + c] = fmaxf(acc, 0.0f);
    }
    __syncthreads();

    // stage w2 (8192 floats)
    {
        const float4* src = reinterpret_cast<const float4*>(w2);
        float4* dst = reinterpret_cast<float4*>(wbuf);
#pragma unroll
        for (int t = 0; t < 8; ++t) dst[tid + t * 256] = src[tid + t * 256];
    }
    __syncthreads();

    // phase 6: hb[p][dd] += zb[p] @ w2 + b2  (TILE*128 = 512 outputs, 2/thread; disjoint rw)
#pragma unroll
    for (int t = 0; t < 2; ++t) {
        int i = t * 256 + tid;
        int p = i >> 7, dd2 = i & 127;
        float acc = b2[dd2] + hb[i];
        const float* wcol = wbuf + dd2;
        const float4* z4 = reinterpret_cast<const float4*>(zb + p * 64);
#pragma unroll 4
        for (int c4 = 0; c4 < 16; ++c4) {
            float w0 = wcol[(c4 * 4 + 0) * DD];
            float w1v = wcol[(c4 * 4 + 1) * DD];
            float w2v = wcol[(c4 * 4 + 2) * DD];
            float w3v = wcol[(c4 * 4 + 3) * DD];
            float4 z = z4[c4];
            acc += z.x * w0 + z.y * w1v + z.z * w2v + z.w * w3v;
        }
        hb[i] = acc;   // each element read+written by this thread only
    }
    __syncthreads();

    // phase 7: out[pos][o] = hb[p] @ wp + bp  (4 positions, o = tid)
    {
        int o = tid;
        float acc[TILE];
        float b = bp[o];
#pragma unroll
        for (int p = 0; p < TILE; ++p) acc[p] = b;
        const float* wcol = wp + o;
#pragma unroll 2
        for (int j4 = 0; j4 < DD / 4; ++j4) {
            float w0 = wcol[(size_t)(j4 * 4 + 0) * HIDSZ];
            float w1v = wcol[(size_t)(j4 * 4 + 1) * HIDSZ];
            float w2v = wcol[(size_t)(j4 * 4 + 2) * HIDSZ];
            float w3v = wcol[(size_t)(j4 * 4 + 3) * HIDSZ];
#pragma unroll
            for (int p = 0; p < TILE; ++p) {
                float4 h = reinterpret_cast<const float4*>(hb + p * DD)[j4];
                acc[p] += h.x * w0 + h.y * w1v + h.z * w2v + h.w * w3v;
            }
        }
#pragma unroll
        for (int p = 0; p < TILE; ++p)
            out[((long)(pbase + p)) * HIDSZ + o] = acc[p];
    }
}

extern "C" void kernel_launch(void* const* d_in, const int* in_sizes, int n_in,
                              void* d_out, int out_size) {
    const float* node_embeds = (const float*)d_in[0];
    const float* bases       = (const float*)d_in[1];
    const float* comp        = (const float*)d_in[2];
    const float* root        = (const float*)d_in[3];
    const float* bias        = (const float*)d_in[4];
    const float* w1          = (const float*)d_in[5];
    const float* b1          = (const float*)d_in[6];
    const float* w2          = (const float*)d_in[7];
    const float* b2          = (const float*)d_in[8];
    const float* wp          = (const float*)d_in[9];
    const float* bp          = (const float*)d_in[10];
    const int*   edge_index  = (const int*)d_in[11];
    const int*   edge_type   = (const int*)d_in[12];
    const int*   entity_ids  = (const int*)d_in[13];
    float* out = (float*)d_out;

    const int smem_bytes = (2 * WBUF_F + TILE * DD + TILE * NB * DD + N_REL * NB +
                            TILE * N_REL + TILE * DD + TILE * 64) * 4 + TILE * 4;
    cudaFuncSetAttribute(k_final, cudaFuncAttributeMaxDynamicSharedMemorySize, smem_bytes);

    k_prep<<<PGRID, PTHREADS>>>(node_embeds, edge_index, edge_type, entity_ids);
    k_final<<<N_POS / TILE, 256, smem_bytes>>>(node_embeds, bases, comp, root, bias,
                                               w1, b1, w2, b2, wp, bp,
                                               entity_ids, out);
    (void)in_sizes; (void)n_in; (void)out_size;
}

// round 9
// speedup vs baseline: 1.1495x; 1.1495x over previous
#include <cuda_runtime.h>

#define N_ENTITY 100000
#define DD 128
#define HIDSZ 256
#define N_REL 48
#define NB 8
#define NEDGE 1000000
#define N_POS 1024
#define CAP (1 << 17)
#define ZMAX (N_POS * N_REL)
#define TILE 8
#define NCHUNK 36
#define NCHALF 18
#define CROWS 32
#define WBUF_F (CROWS * DD)   // 4096 floats per staging buffer
#define PGRID 148
#define PTHREADS 1024

// ---- device scratch (no allocation allowed) ----
__device__ int   g_map[N_ENTITY];
__device__ int   g_deg[N_POS * N_REL];
__device__ float g_s[N_POS * N_REL * DD];
__device__ int4  g_ce[CAP];
__device__ int   g_cnt;
__device__ int   g_zlist[ZMAX];
__device__ int   g_zcnt;
__device__ int   g_bar_count;
__device__ volatile int g_bar_gen;

__device__ __forceinline__ void grid_bar() {
    __syncthreads();
    if (threadIdx.x == 0) {
        int gen = g_bar_gen;
        __threadfence();
        if (atomicAdd(&g_bar_count, 1) == (int)gridDim.x - 1) {
            g_bar_count = 0;
            __threadfence();
            g_bar_gen = gen + 1;
        } else {
            while (g_bar_gen == gen) { }
        }
        __threadfence();
    }
    __syncthreads();
}

// ==== Kernel A: persistent prep (unchanged, verified) ====
__global__ __launch_bounds__(PTHREADS)
void k_prep(const float* __restrict__ x,
            const int* __restrict__ ei, const int* __restrict__ et,
            const int* __restrict__ ids) {
    const int tid  = threadIdx.x;
    const int gtid = blockIdx.x * PTHREADS + tid;
    const int NT   = gridDim.x * PTHREADS;

    for (int i = gtid; i < N_ENTITY; i += NT) g_map[i] = 0x7fffffff;
    for (int i = gtid; i < N_POS * N_REL; i += NT) g_deg[i] = 0;
    if (gtid == 0) { g_cnt = 0; g_zcnt = 0; }
    grid_bar();

    if (gtid < N_POS) atomicMin(&g_map[ids[gtid]], gtid);
    grid_bar();

    for (int t = gtid; t < NEDGE / 4; t += NT) {
        int4 dst4 = reinterpret_cast<const int4*>(ei + NEDGE)[t];
        int ds[4] = {dst4.x, dst4.y, dst4.z, dst4.w};
#pragma unroll
        for (int q = 0; q < 4; ++q) {
            int e = t * 4 + q;
            int slot = g_map[ds[q]];
            if (slot < N_POS) {
                int rel = __ldg(&et[e]);
                int row = slot * N_REL + rel;
                int old = atomicAdd(&g_deg[row], 1);
                if (old == 1) {
                    int zp = atomicAdd(&g_zcnt, 1);
                    if (zp < ZMAX) g_zlist[zp] = row;
                }
                int p = atomicAdd(&g_cnt, 1);
                if (p < CAP) g_ce[p] = make_int4(__ldg(&ei[e]), slot, rel, 0);
            }
        }
    }
    grid_bar();

    {
        int warp = gtid >> 5, lane = tid & 31, nw = NT >> 5;
        int nz = *(volatile int*)&g_zcnt; if (nz > ZMAX) nz = ZMAX;
        float4 z = make_float4(0.f, 0.f, 0.f, 0.f);
        for (int i = warp; i < nz; i += nw) {
            int row = g_zlist[i];
            reinterpret_cast<float4*>(g_s + (size_t)row * DD)[lane] = z;
        }
    }
    grid_bar();

    {
        int warp = gtid >> 5, lane = tid & 31, nw = NT >> 5;
        int cnt = *(volatile int*)&g_cnt; if (cnt > CAP) cnt = CAP;
        for (int i = warp; i < cnt; i += nw) {
            int4 ce = g_ce[i];
            int row = ce.y * N_REL + ce.z;
            int dg = g_deg[row];
            float4 xv = reinterpret_cast<const float4*>(x + (long)ce.x * DD)[lane];
            float* sp = &g_s[(size_t)row * DD + lane * 4];
            if (dg == 1) {
                *reinterpret_cast<float4*>(sp) = xv;
            } else {
                atomicAdd(sp + 0, xv.x);
                atomicAdd(sp + 1, xv.y);
                atomicAdd(sp + 2, xv.z);
                atomicAdd(sp + 3, xv.w);
            }
        }
    }
}

// ==== Kernel B: TILE=8, 512 threads, 2x2 register blocking + K-split ====
__global__ __launch_bounds__(512)
void k_final(const float* __restrict__ x, const float* __restrict__ bases,
             const float* __restrict__ comp, const float* __restrict__ root,
             const float* __restrict__ bias,
             const float* __restrict__ w1, const float* __restrict__ b1,
             const float* __restrict__ w2, const float* __restrict__ b2,
             const float* __restrict__ wp, const float* __restrict__ bp,
             const int* __restrict__ ids, float* __restrict__ out) {
    extern __shared__ float sm[];
    float* wbuf  = sm;                        // 2 halves * 2 bufs * 4096 = 16384 floats
    float* xs    = wbuf + 4 * WBUF_F;         // 1024
    float* vv    = xs + TILE * DD;            // 8192
    float* compS = vv + TILE * NB * DD;       // 384
    float* normS = compS + N_REL * NB;        // 384
    float* hb    = normS + TILE * N_REL;      // 1024
    float* zb    = hb + TILE * DD;            // 512
    float* red   = zb + TILE * 64;            // 1024 (K-split partials)
    int*  canon  = (int*)(red + 1024);        // 8 ints

    const int tid = threadIdx.x;
    const int kh  = tid >> 8;        // K-half 0/1
    const int u   = tid & 255;       // lane within half
    const int sg  = u >> 6;          // 0..3 -> positions {2sg, 2sg+1}
    const int d0  = (u & 63) * 2;    // 2 d-columns
    const int pbase = blockIdx.x * TILE;

    if (tid < TILE) canon[tid] = g_map[ids[pbase + tid]];
    for (int i = tid; i < TILE * DD; i += 512) {
        int p = i >> 7;
        xs[i] = x[(long)ids[pbase + p] * DD + (i & 127)];
    }
    if (tid < N_REL * NB) compS[tid] = comp[tid];
    __syncthreads();
    if (tid < TILE * N_REL) {
        int p = tid / N_REL, r = tid % N_REL;
        int dg = g_deg[canon[p] * N_REL + r];
        normS[tid] = dg > 0 ? 1.0f / (float)dg : 0.0f;
    }

    // preload first chunk of this K-half into registers
    float4 stage[4];
    float* mywbuf = wbuf + kh * 2 * WBUF_F;
    {
        int cc = kh * NCHALF;
        int m = cc >> 2, j0 = (cc & 3) * CROWS;
        const float* wsrc = (m == 0) ? (root + j0 * DD)
                                     : (bases + ((size_t)(m - 1) * DD + j0) * DD);
        const float4* src = reinterpret_cast<const float4*>(wsrc);
#pragma unroll
        for (int t = 0; t < 4; ++t) stage[t] = src[u + t * 256];
    }
    __syncthreads();

    // ---- phase 2: vv[p][k][d] (4 groups of 128 threads, 2 pos each) ----
    {
        const int g2 = tid >> 7;     // 0..3
        const int d  = tid & 127;
#pragma unroll
        for (int p = 0; p < 2; ++p) {
            int pp = g2 * 2 + p;
            const float* srow = &g_s[(size_t)canon[pp] * N_REL * DD + d];
            float acc[NB];
#pragma unroll
            for (int k = 0; k < NB; ++k) acc[k] = 0.0f;
            for (int r = 0; r < N_REL; ++r) {
                float nm = normS[pp * N_REL + r];
                if (nm != 0.0f) {
                    float sv = srow[r * DD] * nm;
#pragma unroll
                    for (int k = 0; k < NB; ++k) acc[k] += sv * compS[r * NB + k];
                }
            }
#pragma unroll
            for (int k = 0; k < NB; ++k) vv[(pp * NB + k) * DD + d] = acc[k];
        }
    }
    // store preloaded chunk
    {
        float4* dst = reinterpret_cast<float4*>(mywbuf);
#pragma unroll
        for (int t = 0; t < 4; ++t) dst[u + t * 256] = stage[t];
    }
    __syncthreads();

    // ---- phase 3: 2x2 blocked GEMM over this thread's K-half ----
    {
        float acc00, acc01, acc10, acc11;
        if (kh == 0) { acc00 = bias[d0]; acc01 = bias[d0 + 1]; acc10 = acc00; acc11 = acc01; }
        else         { acc00 = acc01 = acc10 = acc11 = 0.0f; }
        const int pp0 = sg * 2;
        int buf = 0;
        for (int cl = 0; cl < NCHALF; ++cl) {
            int cc = kh * NCHALF + cl;
            if (cl + 1 < NCHALF) {
                int cn = cc + 1;
                int m = cn >> 2, j0 = (cn & 3) * CROWS;
                const float* wsrc = (m == 0) ? (root + j0 * DD)
                                             : (bases + ((size_t)(m - 1) * DD + j0) * DD);
                const float4* src = reinterpret_cast<const float4*>(wsrc);
#pragma unroll
                for (int t = 0; t < 4; ++t) stage[t] = src[u + t * 256];
            }
            {
                int m = cc >> 2, j0 = (cc & 3) * CROWS;
                const float4* a0 = reinterpret_cast<const float4*>(
                    (m == 0) ? (xs + pp0 * DD + j0)
                             : (vv + (pp0 * NB + (m - 1)) * DD + j0));
                const float4* a1 = reinterpret_cast<const float4*>(
                    (m == 0) ? (xs + (pp0 + 1) * DD + j0)
                             : (vv + ((pp0 + 1) * NB + (m - 1)) * DD + j0));
                const float* wrow = mywbuf + buf * WBUF_F + d0;
#pragma unroll
                for (int jj4 = 0; jj4 < CROWS / 4; ++jj4) {
                    float2 w0 = *reinterpret_cast<const float2*>(wrow + (jj4 * 4 + 0) * DD);
                    float2 w1v = *reinterpret_cast<const float2*>(wrow + (jj4 * 4 + 1) * DD);
                    float2 w2v = *reinterpret_cast<const float2*>(wrow + (jj4 * 4 + 2) * DD);
                    float2 w3v = *reinterpret_cast<const float2*>(wrow + (jj4 * 4 + 3) * DD);
                    float4 v0 = a0[jj4];
                    float4 v1 = a1[jj4];
                    acc00 += v0.x * w0.x + v0.y * w1v.x + v0.z * w2v.x + v0.w * w3v.x;
                    acc01 += v0.x * w0.y + v0.y * w1v.y + v0.z * w2v.y + v0.w * w3v.y;
                    acc10 += v1.x * w0.x + v1.y * w1v.x + v1.z * w2v.x + v1.w * w3v.x;
                    acc11 += v1.x * w0.y + v1.y * w1v.y + v1.z * w2v.y + v1.w * w3v.y;
                }
            }
            if (cl + 1 < NCHALF) {
                float4* dst = reinterpret_cast<float4*>(mywbuf + (buf ^ 1) * WBUF_F);
#pragma unroll
                for (int t = 0; t < 4; ++t) dst[u + t * 256] = stage[t];
                buf ^= 1;
            }
            __syncthreads();
        }
        // K-split combine: half 1 publishes partials, half 0 reduces + residual
        if (kh == 1) {
            red[u * 4 + 0] = acc00; red[u * 4 + 1] = acc01;
            red[u * 4 + 2] = acc10; red[u * 4 + 3] = acc11;
        }
        __syncthreads();
        if (kh == 0) {
            acc00 += red[u * 4 + 0]; acc01 += red[u * 4 + 1];
            acc10 += red[u * 4 + 2]; acc11 += red[u * 4 + 3];
            hb[pp0 * DD + d0]           = acc00 + xs[pp0 * DD + d0];
            hb[pp0 * DD + d0 + 1]       = acc01 + xs[pp0 * DD + d0 + 1];
            hb[(pp0 + 1) * DD + d0]     = acc10 + xs[(pp0 + 1) * DD + d0];
            hb[(pp0 + 1) * DD + d0 + 1] = acc11 + xs[(pp0 + 1) * DD + d0 + 1];
        }
    }
    __syncthreads();

    // ---- stage w1 (8192 floats) ----
    {
        const float4* src = reinterpret_cast<const float4*>(w1);
        float4* dst = reinterpret_cast<float4*>(wbuf);
#pragma unroll
        for (int t = 0; t < 4; ++t) dst[tid + t * 512] = src[tid + t * 512];
    }
    __syncthreads();

    // ---- phase 5: zb[p][c] = relu(hb[p] @ w1 + b1)  (512 outputs, 1/thread) ----
    {
        int p = tid >> 6, c = tid & 63;
        float acc = b1[c];
        const float* wcol = wbuf + c;
        const float4* h4 = reinterpret_cast<const float4*>(hb + p * DD);
#pragma unroll 4
        for (int j4 = 0; j4 < DD / 4; ++j4) {
            float w0 = wcol[(j4 * 4 + 0) * 64];
            float w1v = wcol[(j4 * 4 + 1) * 64];
            float w2v = wcol[(j4 * 4 + 2) * 64];
            float w3v = wcol[(j4 * 4 + 3) * 64];
            float4 h = h4[j4];
            acc += h.x * w0 + h.y * w1v + h.z * w2v + h.w * w3v;
        }
        zb[p * 64 + c] = fmaxf(acc, 0.0f);
    }
    __syncthreads();

    // ---- stage w2 (8192 floats) ----
    {
        const float4* src = reinterpret_cast<const float4*>(w2);
        float4* dst = reinterpret_cast<float4*>(wbuf);
#pragma unroll
        for (int t = 0; t < 4; ++t) dst[tid + t * 512] = src[tid + t * 512];
    }
    __syncthreads();

    // ---- phase 6: hb[p][dd] += zb[p] @ w2 + b2  (1024 outputs, 2/thread, disjoint) ----
#pragma unroll
    for (int t = 0; t < 2; ++t) {
        int i = t * 512 + tid;
        int p = i >> 7, dd2 = i & 127;
        float acc = b2[dd2] + hb[i];
        const float* wcol = wbuf + dd2;
        const float4* z4 = reinterpret_cast<const float4*>(zb + p * 64);
#pragma unroll 4
        for (int c4 = 0; c4 < 16; ++c4) {
            float w0 = wcol[(c4 * 4 + 0) * DD];
            float w1v = wcol[(c4 * 4 + 1) * DD];
            float w2v = wcol[(c4 * 4 + 2) * DD];
            float w3v = wcol[(c4 * 4 + 3) * DD];
            float4 z = z4[c4];
            acc += z.x * w0 + z.y * w1v + z.z * w2v + z.w * w3v;
        }
        hb[i] = acc;
    }
    __syncthreads();

    // ---- phase 7: out = hb @ wp + bp (o = tid&255, 4 positions per thread) ----
    {
        int o = tid & 255, ph = tid >> 8;
        float acc[4];
        float b = bp[o];
#pragma unroll
        for (int p = 0; p < 4; ++p) acc[p] = b;
        const float* wcol = wp + o;
#pragma unroll 2
        for (int j4 = 0; j4 < DD / 4; ++j4) {
            float w0 = wcol[(size_t)(j4 * 4 + 0) * HIDSZ];
            float w1v = wcol[(size_t)(j4 * 4 + 1) * HIDSZ];
            float w2v = wcol[(size_t)(j4 * 4 + 2) * HIDSZ];
            float w3v = wcol[(size_t)(j4 * 4 + 3) * HIDSZ];
#pragma unroll
            for (int p = 0; p < 4; ++p) {
                float4 h = reinterpret_cast<const float4*>(hb + (ph * 4 + p) * DD)[j4];
                acc[p] += h.x * w0 + h.y * w1v + h.z * w2v + h.w * w3v;
            }
        }
#pragma unroll
        for (int p = 0; p < 4; ++p)
            out[((long)(pbase + ph * 4 + p)) * HIDSZ + o] = acc[p];
    }
}

extern "C" void kernel_launch(void* const* d_in, const int* in_sizes, int n_in,
                              void* d_out, int out_size) {
    const float* node_embeds = (const float*)d_in[0];
    const float* bases       = (const float*)d_in[1];
    const float* comp        = (const float*)d_in[2];
    const float* root        = (const float*)d_in[3];
    const float* bias        = (const float*)d_in[4];
    const float* w1          = (const float*)d_in[5];
    const float* b1          = (const float*)d_in[6];
    const float* w2          = (const float*)d_in[7];
    const float* b2          = (const float*)d_in[8];
    const float* wp          = (const float*)d_in[9];
    const float* bp          = (const float*)d_in[10];
    const int*   edge_index  = (const int*)d_in[11];
    const int*   edge_type   = (const int*)d_in[12];
    const int*   entity_ids  = (const int*)d_in[13];
    float* out = (float*)d_out;

    const int smem_bytes = (4 * WBUF_F + TILE * DD + TILE * NB * DD + N_REL * NB +
                            TILE * N_REL + TILE * DD + TILE * 64 + 1024) * 4 + TILE * 4;
    cudaFuncSetAttribute(k_final, cudaFuncAttributeMaxDynamicSharedMemorySize, smem_bytes);

    k_prep<<<PGRID, PTHREADS>>>(node_embeds, edge_index, edge_type, entity_ids);
    k_final<<<N_POS / TILE, 512, smem_bytes>>>(node_embeds, bases, comp, root, bias,
                                               w1, b1, w2, b2, wp, bp,
                                               entity_ids, out);
    (void)in_sizes; (void)n_in; (void)out_size;
}

// round 10
// speedup vs baseline: 1.2487x; 1.0863x over previous
#include <cuda_runtime.h>

#define N_ENTITY 100000
#define DD 128
#define HIDSZ 256
#define N_REL 48
#define NB 8
#define NEDGE 1000000
#define N_POS 1024
#define CAP (1 << 17)
#define ZMAX (N_POS * N_REL)
#define TILE 8
#define KTOT 1152          // 128 root + 8*128 bases rows
#define PGRID 148
#define PTHREADS 1024

// ---- device scratch (no allocation allowed) ----
__device__ int   g_map[N_ENTITY];
__device__ int   g_deg[N_POS * N_REL];
__device__ float g_s[N_POS * N_REL * DD];
__device__ int4  g_ce[CAP];
__device__ int   g_cnt;
__device__ int   g_zlist[ZMAX];
__device__ int   g_zcnt;
__device__ int   g_bar_count;
__device__ volatile int g_bar_gen;

__device__ __forceinline__ void grid_bar() {
    __syncthreads();
    if (threadIdx.x == 0) {
        int gen = g_bar_gen;
        __threadfence();
        if (atomicAdd(&g_bar_count, 1) == (int)gridDim.x - 1) {
            g_bar_count = 0;
            __threadfence();
            g_bar_gen = gen + 1;
        } else {
            while (g_bar_gen == gen) { }
        }
        __threadfence();
    }
    __syncthreads();
}

// ==== Kernel A: persistent prep (unchanged, verified) ====
__global__ __launch_bounds__(PTHREADS)
void k_prep(const float* __restrict__ x,
            const int* __restrict__ ei, const int* __restrict__ et,
            const int* __restrict__ ids) {
    const int tid  = threadIdx.x;
    const int gtid = blockIdx.x * PTHREADS + tid;
    const int NT   = gridDim.x * PTHREADS;

    for (int i = gtid; i < N_ENTITY; i += NT) g_map[i] = 0x7fffffff;
    for (int i = gtid; i < N_POS * N_REL; i += NT) g_deg[i] = 0;
    if (gtid == 0) { g_cnt = 0; g_zcnt = 0; }
    grid_bar();

    if (gtid < N_POS) atomicMin(&g_map[ids[gtid]], gtid);
    grid_bar();

    for (int t = gtid; t < NEDGE / 4; t += NT) {
        int4 dst4 = reinterpret_cast<const int4*>(ei + NEDGE)[t];
        int ds[4] = {dst4.x, dst4.y, dst4.z, dst4.w};
#pragma unroll
        for (int q = 0; q < 4; ++q) {
            int e = t * 4 + q;
            int slot = g_map[ds[q]];
            if (slot < N_POS) {
                int rel = __ldg(&et[e]);
                int row = slot * N_REL + rel;
                int old = atomicAdd(&g_deg[row], 1);
                if (old == 1) {
                    int zp = atomicAdd(&g_zcnt, 1);
                    if (zp < ZMAX) g_zlist[zp] = row;
                }
                int p = atomicAdd(&g_cnt, 1);
                if (p < CAP) g_ce[p] = make_int4(__ldg(&ei[e]), slot, rel, 0);
            }
        }
    }
    grid_bar();

    {
        int warp = gtid >> 5, lane = tid & 31, nw = NT >> 5;
        int nz = *(volatile int*)&g_zcnt; if (nz > ZMAX) nz = ZMAX;
        float4 z = make_float4(0.f, 0.f, 0.f, 0.f);
        for (int i = warp; i < nz; i += nw) {
            int row = g_zlist[i];
            reinterpret_cast<float4*>(g_s + (size_t)row * DD)[lane] = z;
        }
    }
    grid_bar();

    {
        int warp = gtid >> 5, lane = tid & 31, nw = NT >> 5;
        int cnt = *(volatile int*)&g_cnt; if (cnt > CAP) cnt = CAP;
        for (int i = warp; i < cnt; i += nw) {
            int4 ce = g_ce[i];
            int row = ce.y * N_REL + ce.z;
            int dg = g_deg[row];
            float4 xv = reinterpret_cast<const float4*>(x + (long)ce.x * DD)[lane];
            float* sp = &g_s[(size_t)row * DD + lane * 4];
            if (dg == 1) {
                *reinterpret_cast<float4*>(sp) = xv;
            } else {
                atomicAdd(sp + 0, xv.x);
                atomicAdd(sp + 1, xv.y);
                atomicAdd(sp + 2, xv.z);
                atomicAdd(sp + 3, xv.w);
            }
        }
    }
}

// ==== Kernel B: TILE=8, 512 threads; phase3 = transposed acts + L2 weights ====
__global__ __launch_bounds__(512)
void k_final(const float* __restrict__ x, const float* __restrict__ bases,
             const float* __restrict__ comp, const float* __restrict__ root,
             const float* __restrict__ bias,
             const float* __restrict__ w1, const float* __restrict__ b1,
             const float* __restrict__ w2, const float* __restrict__ b2,
             const float* __restrict__ wp, const float* __restrict__ bp,
             const int* __restrict__ ids, float* __restrict__ out) {
    extern __shared__ float sm[];
    float* aT    = sm;                     // [KTOT][8] = 9216 floats (transposed acts)
    float* compS = aT + KTOT * TILE;       // 384
    float* normS = compS + N_REL * NB;     // 384
    float* hb    = normS + TILE * N_REL;   // 1024  [pos][d]
    float* zb    = hb + TILE * DD;         // 512   [pos][c]
    float* red   = zb + TILE * 64;         // 8192  (K-split partials; later w1/w2 stage)
    int*  canon  = (int*)(red + 8192);     // 8 ints

    const int tid = threadIdx.x;
    const int pbase = blockIdx.x * TILE;

    if (tid < TILE) canon[tid] = g_map[ids[pbase + tid]];
    // xs -> aT[j<128][p] (transposed)
    for (int i = tid; i < TILE * DD; i += 512) {
        int p = i >> 7, d = i & 127;
        aT[d * TILE + p] = x[(long)ids[pbase + p] * DD + d];
    }
    if (tid < N_REL * NB) compS[tid] = comp[tid];
    __syncthreads();
    if (tid < TILE * N_REL) {
        int p = tid / N_REL, r = tid % N_REL;
        int dg = g_deg[canon[p] * N_REL + r];
        normS[tid] = dg > 0 ? 1.0f / (float)dg : 0.0f;
    }
    __syncthreads();

    // ---- phase 2: vv -> aT[128 + k*128 + d][pp] ----
    {
        const int g2 = tid >> 7;   // 0..3
        const int d  = tid & 127;
#pragma unroll
        for (int p = 0; p < 2; ++p) {
            int pp = g2 * 2 + p;
            const float* srow = &g_s[(size_t)canon[pp] * N_REL * DD + d];
            float acc[NB];
#pragma unroll
            for (int k = 0; k < NB; ++k) acc[k] = 0.0f;
            for (int r = 0; r < N_REL; ++r) {
                float nm = normS[pp * N_REL + r];
                if (nm != 0.0f) {
                    float sv = srow[r * DD] * nm;
#pragma unroll
                    for (int k = 0; k < NB; ++k) acc[k] += sv * compS[r * NB + k];
                }
            }
#pragma unroll
            for (int k = 0; k < NB; ++k)
                aT[((k + 1) * DD + d) * TILE + pp] = acc[k];
        }
    }
    __syncthreads();

    // ---- phase 3: GEMM, K-split 8, 8pos x 2col per thread, weights from L2 ----
    {
        const int kh = tid >> 6;       // 0..7 (K slice: 144 rows each)
        const int u  = tid & 63;       // column pair
        const int c0 = u * 2;
        float acc[16];
#pragma unroll
        for (int i = 0; i < 16; ++i) acc[i] = 0.0f;

        const int r0 = kh * (KTOT / 8);
        const int r1 = r0 + (KTOT / 8);

#define P3_BODY(WROW, J) { \
        float2 w = *reinterpret_cast<const float2*>((WROW) + c0); \
        const float4* ap = reinterpret_cast<const float4*>(aT + (J) * TILE); \
        float4 a0 = ap[0], a1 = ap[1]; \
        acc[0]  += a0.x * w.x; acc[1]  += a0.x * w.y; \
        acc[2]  += a0.y * w.x; acc[3]  += a0.y * w.y; \
        acc[4]  += a0.z * w.x; acc[5]  += a0.z * w.y; \
        acc[6]  += a0.w * w.x; acc[7]  += a0.w * w.y; \
        acc[8]  += a1.x * w.x; acc[9]  += a1.x * w.y; \
        acc[10] += a1.y * w.x; acc[11] += a1.y * w.y; \
        acc[12] += a1.z * w.x; acc[13] += a1.z * w.y; \
        acc[14] += a1.w * w.x; acc[15] += a1.w * w.y; }

        // root segment (only kh==0 touches j<128)
        int jr_end = (r1 < DD) ? r1 : DD;
#pragma unroll 4
        for (int j = r0; j < jr_end; ++j) P3_BODY(root + j * DD, j);
        // bases segment (contiguous [1024][128]; index j-128)
        int jb_start = (r0 > DD) ? r0 : DD;
#pragma unroll 4
        for (int j = jb_start; j < r1; ++j) P3_BODY(bases + (size_t)(j - DD) * DD, j);
#undef P3_BODY

        // publish partials
#pragma unroll
        for (int p = 0; p < 8; ++p)
            *reinterpret_cast<float2*>(red + kh * 1024 + p * DD + c0) =
                make_float2(acc[p * 2], acc[p * 2 + 1]);
    }
    __syncthreads();

    // reduce partials + bias + residual -> hb[pos][d]
    for (int i = tid; i < TILE * DD; i += 512) {
        int p = i >> 7, d = i & 127;
        float s = bias[d] + aT[d * TILE + p];   // + xs residual
#pragma unroll
        for (int k = 0; k < 8; ++k) s += red[k * 1024 + i];
        hb[i] = s;
    }
    __syncthreads();

    // ---- stage w1 into red (8192 floats) ----
    {
        const float4* src = reinterpret_cast<const float4*>(w1);
        float4* dst = reinterpret_cast<float4*>(red);
#pragma unroll
        for (int t = 0; t < 4; ++t) dst[tid + t * 512] = src[tid + t * 512];
    }
    __syncthreads();

    // ---- phase 5: zb[p][c] = relu(hb[p] @ w1 + b1) ----
    {
        int p = tid >> 6, c = tid & 63;
        float acc = b1[c];
        const float* wcol = red + c;
        const float4* h4 = reinterpret_cast<const float4*>(hb + p * DD);
#pragma unroll 4
        for (int j4 = 0; j4 < DD / 4; ++j4) {
            float w0 = wcol[(j4 * 4 + 0) * 64];
            float w1v = wcol[(j4 * 4 + 1) * 64];
            float w2v = wcol[(j4 * 4 + 2) * 64];
            float w3v = wcol[(j4 * 4 + 3) * 64];
            float4 h = h4[j4];
            acc += h.x * w0 + h.y * w1v + h.z * w2v + h.w * w3v;
        }
        zb[p * 64 + c] = fmaxf(acc, 0.0f);
    }
    __syncthreads();

    // ---- stage w2 into red ----
    {
        const float4* src = reinterpret_cast<const float4*>(w2);
        float4* dst = reinterpret_cast<float4*>(red);
#pragma unroll
        for (int t = 0; t < 4; ++t) dst[tid + t * 512] = src[tid + t * 512];
    }
    __syncthreads();

    // ---- phase 6: hb[p][dd] += zb[p] @ w2 + b2 ----
#pragma unroll
    for (int t = 0; t < 2; ++t) {
        int i = t * 512 + tid;
        int p = i >> 7, dd2 = i & 127;
        float acc = b2[dd2] + hb[i];
        const float* wcol = red + dd2;
        const float4* z4 = reinterpret_cast<const float4*>(zb + p * 64);
#pragma unroll 4
        for (int c4 = 0; c4 < 16; ++c4) {
            float w0 = wcol[(c4 * 4 + 0) * DD];
            float w1v = wcol[(c4 * 4 + 1) * DD];
            float w2v = wcol[(c4 * 4 + 2) * DD];
            float w3v = wcol[(c4 * 4 + 3) * DD];
            float4 z = z4[c4];
            acc += z.x * w0 + z.y * w1v + z.z * w2v + z.w * w3v;
        }
        hb[i] = acc;
    }
    __syncthreads();

    // ---- phase 7: out = hb @ wp + bp ----
    {
        int o = tid & 255, ph = tid >> 8;
        float acc[4];
        float b = bp[o];
#pragma unroll
        for (int p = 0; p < 4; ++p) acc[p] = b;
        const float* wcol = wp + o;
#pragma unroll 2
        for (int j4 = 0; j4 < DD / 4; ++j4) {
            float w0 = wcol[(size_t)(j4 * 4 + 0) * HIDSZ];
            float w1v = wcol[(size_t)(j4 * 4 + 1) * HIDSZ];
            float w2v = wcol[(size_t)(j4 * 4 + 2) * HIDSZ];
            float w3v = wcol[(size_t)(j4 * 4 + 3) * HIDSZ];
#pragma unroll
            for (int p = 0; p < 4; ++p) {
                float4 h = reinterpret_cast<const float4*>(hb + (ph * 4 + p) * DD)[j4];
                acc[p] += h.x * w0 + h.y * w1v + h.z * w2v + h.w * w3v;
            }
        }
#pragma unroll
        for (int p = 0; p < 4; ++p)
            out[((long)(pbase + ph * 4 + p)) * HIDSZ + o] = acc[p];
    }
}

extern "C" void kernel_launch(void* const* d_in, const int* in_sizes, int n_in,
                              void* d_out, int out_size) {
    const float* node_embeds = (const float*)d_in[0];
    const float* bases       = (const float*)d_in[1];
    const float* comp        = (const float*)d_in[2];
    const float* root        = (const float*)d_in[3];
    const float* bias        = (const float*)d_in[4];
    const float* w1          = (const float*)d_in[5];
    const float* b1          = (const float*)d_in[6];
    const float* w2          = (const float*)d_in[7];
    const float* b2          = (const float*)d_in[8];
    const float* wp          = (const float*)d_in[9];
    const float* bp          = (const float*)d_in[10];
    const int*   edge_index  = (const int*)d_in[11];
    const int*   edge_type   = (const int*)d_in[12];
    const int*   entity_ids  = (const int*)d_in[13];
    float* out = (float*)d_out;

    const int smem_bytes = (KTOT * TILE + N_REL * NB + TILE * N_REL +
                            TILE * DD + TILE * 64 + 8192) * 4 + TILE * 4;
    cudaFuncSetAttribute(k_final, cudaFuncAttributeMaxDynamicSharedMemorySize, smem_bytes);

    k_prep<<<PGRID, PTHREADS>>>(node_embeds, edge_index, edge_type, entity_ids);
    k_final<<<N_POS / TILE, 512, smem_bytes>>>(node_embeds, bases, comp, root, bias,
                                               w1, b1, w2, b2, wp, bp,
                                               entity_ids, out);
    (void)in_sizes; (void)n_in; (void)out_size;
}

// round 11
// speedup vs baseline: 1.4008x; 1.1218x over previous
#include <cuda_runtime.h>

#define N_ENTITY 100000
#define DD 128
#define HIDSZ 256
#define N_REL 48
#define NB 8
#define NEDGE 1000000
#define N_POS 1024
#define CAP (1 << 17)
#define ZMAX (N_POS * N_REL)
#define TILE 4
#define KTOT 1152          // 128 root + 8*128 bases rows
#define KSLICE (KTOT / 8)  // 144 rows per K-slice
#define PGRID 148
#define PTHREADS 1024

// ---- device scratch (no allocation allowed) ----
__device__ int   g_map[N_ENTITY];
__device__ int   g_deg[N_POS * N_REL];
__device__ float g_s[N_POS * N_REL * DD];
__device__ int4  g_ce[CAP];
__device__ int   g_cnt;
__device__ int   g_zlist[ZMAX];
__device__ int   g_zcnt;
__device__ int   g_bar_count;
__device__ volatile int g_bar_gen;

__device__ __forceinline__ void grid_bar() {
    __syncthreads();
    if (threadIdx.x == 0) {
        int gen = g_bar_gen;
        __threadfence();
        if (atomicAdd(&g_bar_count, 1) == (int)gridDim.x - 1) {
            g_bar_count = 0;
            __threadfence();
            g_bar_gen = gen + 1;
        } else {
            while (g_bar_gen == gen) { }
        }
        __threadfence();
    }
    __syncthreads();
}

// ==== Kernel A: persistent prep (unchanged, verified) ====
__global__ __launch_bounds__(PTHREADS)
void k_prep(const float* __restrict__ x,
            const int* __restrict__ ei, const int* __restrict__ et,
            const int* __restrict__ ids) {
    const int tid  = threadIdx.x;
    const int gtid = blockIdx.x * PTHREADS + tid;
    const int NT   = gridDim.x * PTHREADS;

    for (int i = gtid; i < N_ENTITY; i += NT) g_map[i] = 0x7fffffff;
    for (int i = gtid; i < N_POS * N_REL; i += NT) g_deg[i] = 0;
    if (gtid == 0) { g_cnt = 0; g_zcnt = 0; }
    grid_bar();

    if (gtid < N_POS) atomicMin(&g_map[ids[gtid]], gtid);
    grid_bar();

    for (int t = gtid; t < NEDGE / 4; t += NT) {
        int4 dst4 = reinterpret_cast<const int4*>(ei + NEDGE)[t];
        int ds[4] = {dst4.x, dst4.y, dst4.z, dst4.w};
#pragma unroll
        for (int q = 0; q < 4; ++q) {
            int e = t * 4 + q;
            int slot = g_map[ds[q]];
            if (slot < N_POS) {
                int rel = __ldg(&et[e]);
                int row = slot * N_REL + rel;
                int old = atomicAdd(&g_deg[row], 1);
                if (old == 1) {
                    int zp = atomicAdd(&g_zcnt, 1);
                    if (zp < ZMAX) g_zlist[zp] = row;
                }
                int p = atomicAdd(&g_cnt, 1);
                if (p < CAP) g_ce[p] = make_int4(__ldg(&ei[e]), slot, rel, 0);
            }
        }
    }
    grid_bar();

    {
        int warp = gtid >> 5, lane = tid & 31, nw = NT >> 5;
        int nz = *(volatile int*)&g_zcnt; if (nz > ZMAX) nz = ZMAX;
        float4 z = make_float4(0.f, 0.f, 0.f, 0.f);
        for (int i = warp; i < nz; i += nw) {
            int row = g_zlist[i];
            reinterpret_cast<float4*>(g_s + (size_t)row * DD)[lane] = z;
        }
    }
    grid_bar();

    {
        int warp = gtid >> 5, lane = tid & 31, nw = NT >> 5;
        int cnt = *(volatile int*)&g_cnt; if (cnt > CAP) cnt = CAP;
        for (int i = warp; i < cnt; i += nw) {
            int4 ce = g_ce[i];
            int row = ce.y * N_REL + ce.z;
            int dg = g_deg[row];
            float4 xv = reinterpret_cast<const float4*>(x + (long)ce.x * DD)[lane];
            float* sp = &g_s[(size_t)row * DD + lane * 4];
            if (dg == 1) {
                *reinterpret_cast<float4*>(sp) = xv;
            } else {
                atomicAdd(sp + 0, xv.x);
                atomicAdd(sp + 1, xv.y);
                atomicAdd(sp + 2, xv.z);
                atomicAdd(sp + 3, xv.w);
            }
        }
    }
}

// ==== Kernel B: TILE=4, 512 threads, 2 blocks/SM, 8-deep weight prefetch ====
__global__ __launch_bounds__(512, 2)
void k_final(const float* __restrict__ x, const float* __restrict__ bases,
             const float* __restrict__ comp, const float* __restrict__ root,
             const float* __restrict__ bias,
             const float* __restrict__ w1, const float* __restrict__ b1,
             const float* __restrict__ w2, const float* __restrict__ b2,
             const float* __restrict__ wp, const float* __restrict__ bp,
             const int* __restrict__ ids, float* __restrict__ out) {
    extern __shared__ float sm[];
    float* aT    = sm;                     // [KTOT][4] = 4608 floats (transposed acts)
    float* compS = aT + KTOT * TILE;       // 384
    float* normS = compS + N_REL * NB;     // 192
    float* hb    = normS + TILE * N_REL;   // 512   [pos][d]
    float* zb    = hb + TILE * DD;         // 256   [pos][c]
    float* red   = zb + TILE * 64;         // 8192  (K-split partials; later w1/w2 stage)
    int*  canon  = (int*)(red + 8192);     // 4 ints

    const int tid = threadIdx.x;
    const int pbase = blockIdx.x * TILE;

    if (tid < TILE) canon[tid] = g_map[ids[pbase + tid]];
    // x -> aT[d][p] transposed (one elem per thread: TILE*DD = 512)
    {
        int p = tid >> 7, d = tid & 127;
        aT[d * TILE + p] = x[(long)ids[pbase + p] * DD + d];
    }
    if (tid < N_REL * NB) compS[tid] = comp[tid];
    __syncthreads();
    if (tid < TILE * N_REL) {
        int p = tid / N_REL, r = tid % N_REL;
        int dg = g_deg[canon[p] * N_REL + r];
        normS[tid] = dg > 0 ? 1.0f / (float)dg : 0.0f;
    }
    __syncthreads();

    // ---- phase 2: vv -> aT[(k+1)*128 + d][pp]  (4 groups of 128, 1 pos each) ----
    {
        const int pp = tid >> 7;   // 0..3
        const int d  = tid & 127;
        const float* srow = &g_s[(size_t)canon[pp] * N_REL * DD + d];
        float acc[NB];
#pragma unroll
        for (int k = 0; k < NB; ++k) acc[k] = 0.0f;
        for (int r = 0; r < N_REL; ++r) {
            float nm = normS[pp * N_REL + r];
            if (nm != 0.0f) {
                float sv = srow[r * DD] * nm;
#pragma unroll
                for (int k = 0; k < NB; ++k) acc[k] += sv * compS[r * NB + k];
            }
        }
#pragma unroll
        for (int k = 0; k < NB; ++k)
            aT[((k + 1) * DD + d) * TILE + pp] = acc[k];
    }
    __syncthreads();

    // ---- phase 3: GEMM K-split 8; thread = (K-slice, col-pair); 4pos x 2col accs ----
    {
        const int kh = tid >> 6;       // 0..7
        const int u  = tid & 63;
        const int c0 = u * 2;
        float acc[8];
#pragma unroll
        for (int i = 0; i < 8; ++i) acc[i] = 0.0f;

        const int r0 = kh * KSLICE;
        const int r1 = r0 + KSLICE;

        // pipelined segment: rows [jstart, jstart+nrows) with weight base Wb (row 0 = jstart)
        auto run_seg = [&](const float* Wb, int jstart, int nrows) {
            for (int ch = 0; ch < nrows; ch += 8) {
                float2 w[8];
#pragma unroll
                for (int t = 0; t < 8; ++t)
                    w[t] = *reinterpret_cast<const float2*>(Wb + (size_t)(ch + t) * DD + c0);
#pragma unroll
                for (int t = 0; t < 8; ++t) {
                    float4 a = *reinterpret_cast<const float4*>(aT + (jstart + ch + t) * TILE);
                    acc[0] += a.x * w[t].x; acc[1] += a.x * w[t].y;
                    acc[2] += a.y * w[t].x; acc[3] += a.y * w[t].y;
                    acc[4] += a.z * w[t].x; acc[5] += a.z * w[t].y;
                    acc[6] += a.w * w[t].x; acc[7] += a.w * w[t].y;
                }
            }
        };

        if (r0 < DD) {
            // kh == 0: 128 root rows + 16 bases rows
            run_seg(root, 0, DD);
            run_seg(bases, DD, r1 - DD);
        } else {
            run_seg(bases + (size_t)(r0 - DD) * DD, r0, KSLICE);
        }

        // publish partials: red[kh][p][d]  (8 * 512)
#pragma unroll
        for (int p = 0; p < TILE; ++p)
            *reinterpret_cast<float2*>(red + kh * (TILE * DD) + p * DD + c0) =
                make_float2(acc[p * 2], acc[p * 2 + 1]);
    }
    __syncthreads();

    // reduce partials + bias + residual -> hb[pos][d]  (512 = 1/thread)
    {
        int p = tid >> 7, d = tid & 127;
        float s = bias[d] + aT[d * TILE + p];   // + x residual
#pragma unroll
        for (int k = 0; k < 8; ++k) s += red[k * (TILE * DD) + tid];
        hb[tid] = s;
    }
    __syncthreads();

    // ---- stage w1 into red (8192 floats) ----
    {
        const float4* src = reinterpret_cast<const float4*>(w1);
        float4* dst = reinterpret_cast<float4*>(red);
#pragma unroll
        for (int t = 0; t < 4; ++t) dst[tid + t * 512] = src[tid + t * 512];
    }
    __syncthreads();

    // ---- phase 5: zb[p][c] = relu(hb[p] @ w1 + b1)  (256 outputs) ----
    if (tid < TILE * 64) {
        int p = tid >> 6, c = tid & 63;
        float acc = b1[c];
        const float* wcol = red + c;
        const float4* h4 = reinterpret_cast<const float4*>(hb + p * DD);
#pragma unroll 4
        for (int j4 = 0; j4 < DD / 4; ++j4) {
            float w0 = wcol[(j4 * 4 + 0) * 64];
            float w1v = wcol[(j4 * 4 + 1) * 64];
            float w2v = wcol[(j4 * 4 + 2) * 64];
            float w3v = wcol[(j4 * 4 + 3) * 64];
            float4 h = h4[j4];
            acc += h.x * w0 + h.y * w1v + h.z * w2v + h.w * w3v;
        }
        zb[p * 64 + c] = fmaxf(acc, 0.0f);
    }
    __syncthreads();

    // ---- stage w2 into red ----
    {
        const float4* src = reinterpret_cast<const float4*>(w2);
        float4* dst = reinterpret_cast<float4*>(red);
#pragma unroll
        for (int t = 0; t < 4; ++t) dst[tid + t * 512] = src[tid + t * 512];
    }
    __syncthreads();

    // ---- phase 6: hb[p][dd] += zb[p] @ w2 + b2  (512 = 1/thread, disjoint rw) ----
    {
        int p = tid >> 7, dd2 = tid & 127;
        float acc = b2[dd2] + hb[tid];
        const float* wcol = red + dd2;
        const float4* z4 = reinterpret_cast<const float4*>(zb + p * 64);
#pragma unroll 4
        for (int c4 = 0; c4 < 16; ++c4) {
            float w0 = wcol[(c4 * 4 + 0) * DD];
            float w1v = wcol[(c4 * 4 + 1) * DD];
            float w2v = wcol[(c4 * 4 + 2) * DD];
            float w3v = wcol[(c4 * 4 + 3) * DD];
            float4 z = z4[c4];
            acc += z.x * w0 + z.y * w1v + z.z * w2v + z.w * w3v;
        }
        hb[tid] = acc;
    }
    __syncthreads();

    // ---- phase 7: out = hb @ wp + bp  (1024 outputs, 2 pos/thread) ----
    {
        int o = tid & 255, ph = tid >> 8;   // ph 0/1 -> positions {2ph, 2ph+1}
        int p0 = ph * 2;
        float b = bp[o];
        float acc0 = b, acc1 = b;
        const float* wcol = wp + o;
        const float4* h0 = reinterpret_cast<const float4*>(hb + p0 * DD);
        const float4* h1 = reinterpret_cast<const float4*>(hb + (p0 + 1) * DD);
#pragma unroll 4
        for (int j4 = 0; j4 < DD / 4; ++j4) {
            float w0 = wcol[(size_t)(j4 * 4 + 0) * HIDSZ];
            float w1v = wcol[(size_t)(j4 * 4 + 1) * HIDSZ];
            float w2v = wcol[(size_t)(j4 * 4 + 2) * HIDSZ];
            float w3v = wcol[(size_t)(j4 * 4 + 3) * HIDSZ];
            float4 a = h0[j4], c = h1[j4];
            acc0 += a.x * w0 + a.y * w1v + a.z * w2v + a.w * w3v;
            acc1 += c.x * w0 + c.y * w1v + c.z * w2v + c.w * w3v;
        }
        out[((long)(pbase + p0)) * HIDSZ + o] = acc0;
        out[((long)(pbase + p0 + 1)) * HIDSZ + o] = acc1;
    }
}

extern "C" void kernel_launch(void* const* d_in, const int* in_sizes, int n_in,
                              void* d_out, int out_size) {
    const float* node_embeds = (const float*)d_in[0];
    const float* bases       = (const float*)d_in[1];
    const float* comp        = (const float*)d_in[2];
    const float* root        = (const float*)d_in[3];
    const float* bias        = (const float*)d_in[4];
    const float* w1          = (const float*)d_in[5];
    const float* b1          = (const float*)d_in[6];
    const float* w2          = (const float*)d_in[7];
    const float* b2          = (const float*)d_in[8];
    const float* wp          = (const float*)d_in[9];
    const float* bp          = (const float*)d_in[10];
    const int*   edge_index  = (const int*)d_in[11];
    const int*   edge_type   = (const int*)d_in[12];
    const int*   entity_ids  = (const int*)d_in[13];
    float* out = (float*)d_out;

    const int smem_bytes = (KTOT * TILE + N_REL * NB + TILE * N_REL +
                            TILE * DD + TILE * 64 + 8192) * 4 + TILE * 4;
    cudaFuncSetAttribute(k_final, cudaFuncAttributeMaxDynamicSharedMemorySize, smem_bytes);

    k_prep<<<PGRID, PTHREADS>>>(node_embeds, edge_index, edge_type, entity_ids);
    k_final<<<N_POS / TILE, 512, smem_bytes>>>(node_embeds, bases, comp, root, bias,
                                               w1, b1, w2, b2, wp, bp,
                                               entity_ids, out);
    (void)in_sizes; (void)n_in; (void)out_size;
}

// round 12
// speedup vs baseline: 1.4771x; 1.0545x over previous
#include <cuda_runtime.h>

#define N_ENTITY 100000
#define DD 128
#define HIDSZ 256
#define N_REL 48
#define NB 8
#define NEDGE 1000000
#define N_POS 1024
#define CAP (1 << 17)
#define ZMAX (N_POS * N_REL)
#define TILE 4
#define KTOT 1152           // 128 root + 8*128 bases rows
#define NSLICE 16
#define KSLICE (KTOT / NSLICE)   // 72 rows
#define PGRID 148
#define PTHREADS 1024

// ---- device scratch (no allocation allowed) ----
__device__ int   g_map[N_ENTITY];
__device__ int   g_deg[N_POS * N_REL];
__device__ float g_s[N_POS * N_REL * DD];
__device__ float g_w[KTOT * DD];     // root ‖ bases, contiguous
__device__ int4  g_ce[CAP];
__device__ int   g_cnt;
__device__ int   g_zlist[ZMAX];
__device__ int   g_zcnt;
__device__ int   g_bar_count;
__device__ volatile int g_bar_gen;

__device__ __forceinline__ void grid_bar() {
    __syncthreads();
    if (threadIdx.x == 0) {
        int gen = g_bar_gen;
        __threadfence();
        if (atomicAdd(&g_bar_count, 1) == (int)gridDim.x - 1) {
            g_bar_count = 0;
            __threadfence();
            g_bar_gen = gen + 1;
        } else {
            while (g_bar_gen == gen) { }
        }
        __threadfence();
    }
    __syncthreads();
}

// ==== Kernel A: persistent prep ====
__global__ __launch_bounds__(PTHREADS)
void k_prep(const float* __restrict__ x,
            const int* __restrict__ ei, const int* __restrict__ et,
            const int* __restrict__ ids,
            const float* __restrict__ root, const float* __restrict__ bases) {
    const int tid  = threadIdx.x;
    const int gtid = blockIdx.x * PTHREADS + tid;
    const int NT   = gridDim.x * PTHREADS;

    // P0: init + weight concat (g_w consumed by the NEXT kernel launch)
    for (int i = gtid; i < N_ENTITY; i += NT) g_map[i] = 0x7fffffff;
    for (int i = gtid; i < N_POS * N_REL; i += NT) g_deg[i] = 0;
    for (int i = gtid; i < KTOT * DD; i += NT)
        g_w[i] = (i < DD * DD) ? root[i] : bases[i - DD * DD];
    if (gtid == 0) { g_cnt = 0; g_zcnt = 0; }
    grid_bar();

    // P1: scatter (min position canonical)
    if (gtid < N_POS) atomicMin(&g_map[ids[gtid]], gtid);
    grid_bar();

    // P2: edge scan
    for (int t = gtid; t < NEDGE / 4; t += NT) {
        int4 dst4 = reinterpret_cast<const int4*>(ei + NEDGE)[t];
        int ds[4] = {dst4.x, dst4.y, dst4.z, dst4.w};
#pragma unroll
        for (int q = 0; q < 4; ++q) {
            int e = t * 4 + q;
            int slot = g_map[ds[q]];
            if (slot < N_POS) {
                int rel = __ldg(&et[e]);
                int row = slot * N_REL + rel;
                int old = atomicAdd(&g_deg[row], 1);
                if (old == 1) {
                    int zp = atomicAdd(&g_zcnt, 1);
                    if (zp < ZMAX) g_zlist[zp] = row;
                }
                int p = atomicAdd(&g_cnt, 1);
                if (p < CAP) g_ce[p] = make_int4(__ldg(&ei[e]), slot, rel, 0);
            }
        }
    }
    grid_bar();

    // P3: zero deg>=2 rows
    {
        int warp = gtid >> 5, lane = tid & 31, nw = NT >> 5;
        int nz = *(volatile int*)&g_zcnt; if (nz > ZMAX) nz = ZMAX;
        float4 z = make_float4(0.f, 0.f, 0.f, 0.f);
        for (int i = warp; i < nz; i += nw) {
            int row = g_zlist[i];
            reinterpret_cast<float4*>(g_s + (size_t)row * DD)[lane] = z;
        }
    }
    grid_bar();

    // P4: accumulate
    {
        int warp = gtid >> 5, lane = tid & 31, nw = NT >> 5;
        int cnt = *(volatile int*)&g_cnt; if (cnt > CAP) cnt = CAP;
        for (int i = warp; i < cnt; i += nw) {
            int4 ce = g_ce[i];
            int row = ce.y * N_REL + ce.z;
            int dg = g_deg[row];
            float4 xv = reinterpret_cast<const float4*>(x + (long)ce.x * DD)[lane];
            float* sp = &g_s[(size_t)row * DD + lane * 4];
            if (dg == 1) {
                *reinterpret_cast<float4*>(sp) = xv;
            } else {
                atomicAdd(sp + 0, xv.x);
                atomicAdd(sp + 1, xv.y);
                atomicAdd(sp + 2, xv.z);
                atomicAdd(sp + 3, xv.w);
            }
        }
    }
}

// ==== Kernel B: TILE=4, 512 threads, 2 blocks/SM; phase3 = 16-slice float4 GEMM ====
__global__ __launch_bounds__(512, 2)
void k_final(const float* __restrict__ x,
             const float* __restrict__ comp,
             const float* __restrict__ bias,
             const float* __restrict__ w1, const float* __restrict__ b1,
             const float* __restrict__ w2, const float* __restrict__ b2,
             const float* __restrict__ wp, const float* __restrict__ bp,
             const int* __restrict__ ids, float* __restrict__ out) {
    extern __shared__ float sm[];
    float* aT    = sm;                     // [KTOT][4] = 4608 floats
    float* compS = aT + KTOT * TILE;       // 384
    float* normS = compS + N_REL * NB;     // 192
    float* hb    = normS + TILE * N_REL;   // 512   [pos][d]
    float* zb    = hb + TILE * DD;         // 256   [pos][c]
    float* red   = zb + TILE * 64;         // 8192  (16 x 512 partials; later w1/w2 stage)
    int*  canon  = (int*)(red + 8192);     // 4 ints

    const int tid = threadIdx.x;
    const int pbase = blockIdx.x * TILE;

    if (tid < TILE) canon[tid] = g_map[ids[pbase + tid]];
    {
        int p = tid >> 7, d = tid & 127;
        aT[d * TILE + p] = x[(long)ids[pbase + p] * DD + d];
    }
    if (tid < N_REL * NB) compS[tid] = comp[tid];
    __syncthreads();
    if (tid < TILE * N_REL) {
        int p = tid / N_REL, r = tid % N_REL;
        int dg = g_deg[canon[p] * N_REL + r];
        normS[tid] = dg > 0 ? 1.0f / (float)dg : 0.0f;
    }
    __syncthreads();

    // ---- phase 2: vv -> aT[(k+1)*128 + d][pp] ----
    {
        const int pp = tid >> 7;   // 0..3
        const int d  = tid & 127;
        const float* srow = &g_s[(size_t)canon[pp] * N_REL * DD + d];
        float acc[NB];
#pragma unroll
        for (int k = 0; k < NB; ++k) acc[k] = 0.0f;
        for (int r = 0; r < N_REL; ++r) {
            float nm = normS[pp * N_REL + r];
            if (nm != 0.0f) {
                float sv = srow[r * DD] * nm;
#pragma unroll
                for (int k = 0; k < NB; ++k) acc[k] += sv * compS[r * NB + k];
            }
        }
#pragma unroll
        for (int k = 0; k < NB; ++k)
            aT[((k + 1) * DD + d) * TILE + pp] = acc[k];
    }
    __syncthreads();

    // ---- phase 3: GEMM, 16 K-slices x 32 lanes, 4pos x 4col per thread ----
    {
        const int kh = tid >> 5;       // 0..15
        const int c0 = (tid & 31) * 4; // 4 columns
        float acc[16];
#pragma unroll
        for (int i = 0; i < 16; ++i) acc[i] = 0.0f;

        const int r0 = kh * KSLICE;
        const float* Wb = g_w + (size_t)r0 * DD + c0;
        const float* Ab = aT + r0 * TILE;

        for (int ch = 0; ch < KSLICE; ch += 4) {
            float4 w0 = *reinterpret_cast<const float4*>(Wb + (ch + 0) * DD);
            float4 w1v = *reinterpret_cast<const float4*>(Wb + (ch + 1) * DD);
            float4 w2v = *reinterpret_cast<const float4*>(Wb + (ch + 2) * DD);
            float4 w3v = *reinterpret_cast<const float4*>(Wb + (ch + 3) * DD);
#define P3_ROW(W, T) { \
            float4 a = *reinterpret_cast<const float4*>(Ab + (ch + (T)) * TILE); \
            acc[0]  += a.x * (W).x; acc[1]  += a.x * (W).y; acc[2]  += a.x * (W).z; acc[3]  += a.x * (W).w; \
            acc[4]  += a.y * (W).x; acc[5]  += a.y * (W).y; acc[6]  += a.y * (W).z; acc[7]  += a.y * (W).w; \
            acc[8]  += a.z * (W).x; acc[9]  += a.z * (W).y; acc[10] += a.z * (W).z; acc[11] += a.z * (W).w; \
            acc[12] += a.w * (W).x; acc[13] += a.w * (W).y; acc[14] += a.w * (W).z; acc[15] += a.w * (W).w; }
            P3_ROW(w0, 0) P3_ROW(w1v, 1) P3_ROW(w2v, 2) P3_ROW(w3v, 3)
#undef P3_ROW
        }

        // publish partials: red[kh][p][c0..c0+3]
#pragma unroll
        for (int p = 0; p < TILE; ++p)
            *reinterpret_cast<float4*>(red + kh * (TILE * DD) + p * DD + c0) =
                make_float4(acc[p * 4], acc[p * 4 + 1], acc[p * 4 + 2], acc[p * 4 + 3]);
    }
    __syncthreads();

    // reduce 16 partials + bias + residual -> hb[pos][d]
    {
        int p = tid >> 7, d = tid & 127;
        float s = bias[d] + aT[d * TILE + p];
#pragma unroll
        for (int k = 0; k < NSLICE; ++k) s += red[k * (TILE * DD) + tid];
        hb[tid] = s;
    }
    __syncthreads();

    // ---- stage w1 into red ----
    {
        const float4* src = reinterpret_cast<const float4*>(w1);
        float4* dst = reinterpret_cast<float4*>(red);
#pragma unroll
        for (int t = 0; t < 4; ++t) dst[tid + t * 512] = src[tid + t * 512];
    }
    __syncthreads();

    // ---- phase 5: zb[p][c] = relu(hb[p] @ w1 + b1) ----
    if (tid < TILE * 64) {
        int p = tid >> 6, c = tid & 63;
        float acc = b1[c];
        const float* wcol = red + c;
        const float4* h4 = reinterpret_cast<const float4*>(hb + p * DD);
#pragma unroll 4
        for (int j4 = 0; j4 < DD / 4; ++j4) {
            float w0 = wcol[(j4 * 4 + 0) * 64];
            float w1v = wcol[(j4 * 4 + 1) * 64];
            float w2v = wcol[(j4 * 4 + 2) * 64];
            float w3v = wcol[(j4 * 4 + 3) * 64];
            float4 h = h4[j4];
            acc += h.x * w0 + h.y * w1v + h.z * w2v + h.w * w3v;
        }
        zb[p * 64 + c] = fmaxf(acc, 0.0f);
    }
    __syncthreads();

    // ---- stage w2 into red ----
    {
        const float4* src = reinterpret_cast<const float4*>(w2);
        float4* dst = reinterpret_cast<float4*>(red);
#pragma unroll
        for (int t = 0; t < 4; ++t) dst[tid + t * 512] = src[tid + t * 512];
    }
    __syncthreads();

    // ---- phase 6: hb[p][dd] += zb[p] @ w2 + b2 ----
    {
        int p = tid >> 7, dd2 = tid & 127;
        float acc = b2[dd2] + hb[tid];
        const float* wcol = red + dd2;
        const float4* z4 = reinterpret_cast<const float4*>(zb + p * 64);
#pragma unroll 4
        for (int c4 = 0; c4 < 16; ++c4) {
            float w0 = wcol[(c4 * 4 + 0) * DD];
            float w1v = wcol[(c4 * 4 + 1) * DD];
            float w2v = wcol[(c4 * 4 + 2) * DD];
            float w3v = wcol[(c4 * 4 + 3) * DD];
            float4 z = z4[c4];
            acc += z.x * w0 + z.y * w1v + z.z * w2v + z.w * w3v;
        }
        hb[tid] = acc;
    }
    __syncthreads();

    // ---- phase 7: out = hb @ wp + bp (1024 outputs, 2 pos/thread) ----
    {
        int o = tid & 255, ph = tid >> 8;
        int p0 = ph * 2;
        float b = bp[o];
        float acc0 = b, acc1 = b;
        const float* wcol = wp + o;
        const float4* h0 = reinterpret_cast<const float4*>(hb + p0 * DD);
        const float4* h1 = reinterpret_cast<const float4*>(hb + (p0 + 1) * DD);
#pragma unroll 4
        for (int j4 = 0; j4 < DD / 4; ++j4) {
            float w0 = wcol[(size_t)(j4 * 4 + 0) * HIDSZ];
            float w1v = wcol[(size_t)(j4 * 4 + 1) * HIDSZ];
            float w2v = wcol[(size_t)(j4 * 4 + 2) * HIDSZ];
            float w3v = wcol[(size_t)(j4 * 4 + 3) * HIDSZ];
            float4 a = h0[j4], c = h1[j4];
            acc0 += a.x * w0 + a.y * w1v + a.z * w2v + a.w * w3v;
            acc1 += c.x * w0 + c.y * w1v + c.z * w2v + c.w * w3v;
        }
        out[((long)(pbase + p0)) * HIDSZ + o] = acc0;
        out[((long)(pbase + p0 + 1)) * HIDSZ + o] = acc1;
    }
}

extern "C" void kernel_launch(void* const* d_in, const int* in_sizes, int n_in,
                              void* d_out, int out_size) {
    const float* node_embeds = (const float*)d_in[0];
    const float* bases       = (const float*)d_in[1];
    const float* comp        = (const float*)d_in[2];
    const float* root        = (const float*)d_in[3];
    const float* bias        = (const float*)d_in[4];
    const float* w1          = (const float*)d_in[5];
    const float* b1          = (const float*)d_in[6];
    const float* w2          = (const float*)d_in[7];
    const float* b2          = (const float*)d_in[8];
    const float* wp          = (const float*)d_in[9];
    const float* bp          = (const float*)d_in[10];
    const int*   edge_index  = (const int*)d_in[11];
    const int*   edge_type   = (const int*)d_in[12];
    const int*   entity_ids  = (const int*)d_in[13];
    float* out = (float*)d_out;

    const int smem_bytes = (KTOT * TILE + N_REL * NB + TILE * N_REL +
                            TILE * DD + TILE * 64 + 8192) * 4 + TILE * 4;
    cudaFuncSetAttribute(k_final, cudaFuncAttributeMaxDynamicSharedMemorySize, smem_bytes);

    k_prep<<<PGRID, PTHREADS>>>(node_embeds, edge_index, edge_type, entity_ids, root, bases);
    k_final<<<N_POS / TILE, 512, smem_bytes>>>(node_embeds, comp, bias,
                                               w1, b1, w2, b2, wp, bp,
                                               entity_ids, out);
    (void)in_sizes; (void)n_in; (void)out_size;
}